// round 4
// baseline (speedup 1.0000x reference)
#include <cuda_runtime.h>
#include <cuda_bf16.h>
#include <cooperative_groups.h>
#include <cstdint>
#include <cstddef>

namespace cg = cooperative_groups;
using u64 = unsigned long long;

#define BATCH 128
#define TLEN  1024
#define HID   256
#define G4    1024  // 4*HID

// ---------------- packed f32x2 helpers ----------------
__device__ __forceinline__ u64 ffma2(u64 a, u64 b, u64 c) {
    u64 d;
    asm("fma.rn.f32x2 %0, %1, %2, %3;" : "=l"(d) : "l"(a), "l"(b), "l"(c));
    return d;
}
__device__ __forceinline__ u64 pack2(float lo, float hi) {
    u64 r;
    asm("mov.b64 %0, {%1, %2};" : "=l"(r) : "f"(lo), "f"(hi));
    return r;
}
__device__ __forceinline__ float f2lo(u64 v) { return __uint_as_float((unsigned)(v & 0xffffffffull)); }
__device__ __forceinline__ float f2hi(u64 v) { return __uint_as_float((unsigned)(v >> 32)); }

__device__ __forceinline__ float sigm_f(float x) {
    x = fminf(fmaxf(x, -30.f), 30.f);
    return __fdividef(1.f, 1.f + __expf(-x));
}
__device__ __forceinline__ float tanh_f(float x) {
    x = fminf(fmaxf(x, -15.f), 15.f);
    float e = __expf(2.f * x);
    return __fdividef(e - 1.f, e + 1.f);
}

// ---------------- cluster async-store primitives ----------------
__device__ __forceinline__ unsigned smem_u32(const void* p) {
    return (unsigned)__cvta_generic_to_shared(p);
}
__device__ __forceinline__ unsigned mapa_u32(unsigned laddr, unsigned rank) {
    unsigned r;
    asm("mapa.shared::cluster.u32 %0, %1, %2;" : "=r"(r) : "r"(laddr), "r"(rank));
    return r;
}
__device__ __forceinline__ void st_async_f32(unsigned raddr, float v, unsigned rmbar) {
    asm volatile("st.async.shared::cluster.mbarrier::complete_tx::bytes.b32 [%0], %1, [%2];"
                 :: "r"(raddr), "r"(__float_as_uint(v)), "r"(rmbar) : "memory");
}
__device__ __forceinline__ void mbar_init(unsigned mbar, unsigned cnt) {
    asm volatile("mbarrier.init.shared.b64 [%0], %1;" :: "r"(mbar), "r"(cnt) : "memory");
}
__device__ __forceinline__ void mbar_expect_tx(unsigned mbar, unsigned bytes) {
    asm volatile("mbarrier.arrive.expect_tx.shared.b64 _, [%0], %1;"
                 :: "r"(mbar), "r"(bytes) : "memory");
}
__device__ __forceinline__ void mbar_wait_cluster(unsigned mbar, unsigned parity) {
    asm volatile(
        "{\n\t"
        ".reg .pred P;\n"
        "LWAIT_%=:\n\t"
        "mbarrier.try_wait.parity.acquire.cluster.shared::cta.b64 P, [%0], %1, 0x989680;\n\t"
        "@P bra LDONE_%=;\n\t"
        "bra LWAIT_%=;\n"
        "LDONE_%=:\n\t"
        "}"
        :: "r"(mbar), "r"(parity) : "memory");
}

// ---------------- scratch (static device globals) ----------------
__device__ float g_xw[(size_t)BATCH * TLEN * G4];     // 512 MB, reused by both layers
__device__ float g_hseq[(size_t)BATCH * TLEN * HID];  // 128 MB
__device__ float g_hlast[BATCH * HID];

// ---------------------------------------------------------------------------
// GEMM: C[M,1024] = A[M,K] @ B[K,1024] + bias, M=131072, K in {128,256}
// 128x128 tile, BK=16, 256 threads, 8x8 micro-tile, FFMA2, double-buffered.
// ---------------------------------------------------------------------------
__global__ __launch_bounds__(256, 2)
void gemm_bias_kernel(const float* __restrict__ A, const float* __restrict__ B,
                      const float* __restrict__ bias, float* __restrict__ C, int K)
{
    const int N = G4;
    __shared__ float As[2][16][128];
    __shared__ float Bs[2][16][128];

    const int tid = threadIdx.x;
    const int n0  = blockIdx.x * 128;
    const size_t m0 = (size_t)blockIdx.y * 128;
    const int tn = tid & 15;
    const int tm = tid >> 4;

    float4 av[2], bv[2];
    const int NKB = K >> 4;

    auto ldg_tiles = [&](int k0) {
#pragma unroll
        for (int i = 0; i < 2; i++) {
            int idx = tid + i * 256;
            int ar = idx >> 2, kq = idx & 3;
            av[i] = *(const float4*)&A[(m0 + ar) * K + k0 + kq * 4];
            int kr = idx >> 5, nq = idx & 31;
            bv[i] = *(const float4*)&B[(size_t)(k0 + kr) * N + n0 + nq * 4];
        }
    };
    auto sts_tiles = [&](int buf) {
#pragma unroll
        for (int i = 0; i < 2; i++) {
            int idx = tid + i * 256;
            int ar = idx >> 2, kq = idx & 3;
            As[buf][kq * 4 + 0][ar] = av[i].x;
            As[buf][kq * 4 + 1][ar] = av[i].y;
            As[buf][kq * 4 + 2][ar] = av[i].z;
            As[buf][kq * 4 + 3][ar] = av[i].w;
            int kr = idx >> 5, nq = idx & 31;
            *(float4*)&Bs[buf][kr][nq * 4] = bv[i];
        }
    };

    u64 acc[8][4];
#pragma unroll
    for (int m = 0; m < 8; m++)
#pragma unroll
        for (int j = 0; j < 4; j++) acc[m][j] = 0ull;

    ldg_tiles(0);
    sts_tiles(0);
    __syncthreads();

    for (int kb = 0; kb < NKB; kb++) {
        if (kb + 1 < NKB) ldg_tiles((kb + 1) << 4);
        const int buf = kb & 1;
#pragma unroll
        for (int k = 0; k < 16; k++) {
            float4 a0 = *(const float4*)&As[buf][k][tm * 8];
            float4 a1 = *(const float4*)&As[buf][k][tm * 8 + 4];
            u64 b0v = *(const u64*)&Bs[buf][k][2 * tn];
            u64 b1v = *(const u64*)&Bs[buf][k][2 * tn + 32];
            u64 b2v = *(const u64*)&Bs[buf][k][2 * tn + 64];
            u64 b3v = *(const u64*)&Bs[buf][k][2 * tn + 96];
            float aa[8] = {a0.x, a0.y, a0.z, a0.w, a1.x, a1.y, a1.z, a1.w};
#pragma unroll
            for (int m = 0; m < 8; m++) {
                u64 am = pack2(aa[m], aa[m]);
                acc[m][0] = ffma2(am, b0v, acc[m][0]);
                acc[m][1] = ffma2(am, b1v, acc[m][1]);
                acc[m][2] = ffma2(am, b2v, acc[m][2]);
                acc[m][3] = ffma2(am, b3v, acc[m][3]);
            }
        }
        if (kb + 1 < NKB) sts_tiles(buf ^ 1);
        __syncthreads();
    }

    float bias_r[8];
#pragma unroll
    for (int j = 0; j < 4; j++) {
        bias_r[2 * j]     = bias[n0 + 2 * tn + 32 * j];
        bias_r[2 * j + 1] = bias[n0 + 2 * tn + 32 * j + 1];
    }

#pragma unroll
    for (int m = 0; m < 8; m++) {
        size_t row = m0 + tm * 8 + m;
        float* cp = &C[row * N + n0];
#pragma unroll
        for (int j = 0; j < 4; j++) {
            float2 v;
            v.x = f2lo(acc[m][j]) + bias_r[2 * j];
            v.y = f2hi(acc[m][j]) + bias_r[2 * j + 1];
            *(float2*)&cp[2 * tn + 32 * j] = v;
        }
    }
}

// ---------------------------------------------------------------------------
// Persistent-cluster LSTM recurrence, st.async exchange.
// Grid: 128 CTAs = 16 clusters x 8 CTAs, 256 threads.
// Cluster cid owns batch rows [8cid, 8cid+8). CTA rank owns 128 gate columns.
// Phase-1 thread map (quad scheme): lane j = tid&31 owns 4 consecutive
// gate-cols gc = 4j..4j+3 (all within gate j>>3); warp kh = tid>>5 owns
// k-slice [kh*32, kh*32+32). One h float4 feeds 8 FFMA2 (4 cols x lo/hi).
// part[kh][row][gc]: one STS.128 per row per thread.
// Epilogue map: er = tid>>5 (row), ec = tid&31 (h col); 8 partials per gate.
// ---------------------------------------------------------------------------
template <bool WRITE_SEQ>
__global__ void __cluster_dims__(8, 1, 1) __launch_bounds__(256, 1)
lstm_layer(const float* __restrict__ xw, const float* __restrict__ U,
           float* __restrict__ out_seq, float* __restrict__ out_last)
{
    __shared__ float hbuf[2][8][HID];                 // 16 KB, dbl-buffered h
    __shared__ float part[8][8][128];                 // 32 KB, k-group partials
    __shared__ __align__(8) u64 mbars[2];             // tx barriers per buffer

    cg::cluster_group cluster = cg::this_cluster();
    const int tid  = threadIdx.x;
    const int rank = (int)cluster.block_rank();
    const int cid  = blockIdx.x >> 3;
    const int b0   = cid * 8;

    // phase-1 roles
    const int j  = tid & 31;                  // col-quad index, gc = 4j..4j+3
    const int kh = tid >> 5;                  // k block [kh*32, kh*32+32)
    const int colq = (j >> 3) * 256 + rank * 32 + ((4 * j) & 31);

    // epilogue roles
    const int er = tid >> 5;                  // batch row within cluster
    const int ec = tid & 31;                  // h column within rank's 32

    // U slice in registers: 8 kq-groups x (2 k-pairs x 4 cols) = 64 u64.
    // u2[kq*8 + c]     = U[k..k+1][colq+c]   (k = kh*32 + kq*4)
    // u2[kq*8 + 4 + c] = U[k+2..k+3][colq+c]
    u64 u2[64];
#pragma unroll
    for (int kq = 0; kq < 8; kq++) {
        const int k = kh * 32 + kq * 4;
#pragma unroll
        for (int c = 0; c < 4; c++) {
            u2[kq * 8 + c]     = pack2(U[(size_t)k * G4 + colq + c],
                                       U[(size_t)(k + 1) * G4 + colq + c]);
            u2[kq * 8 + 4 + c] = pack2(U[(size_t)(k + 2) * G4 + colq + c],
                                       U[(size_t)(k + 3) * G4 + colq + c]);
        }
    }

    // init smem
    for (int i = tid; i < 2 * 8 * HID; i += 256) ((float*)hbuf)[i] = 0.f;
    const unsigned mbar0 = smem_u32(&mbars[0]);
    if (tid == 0) { mbar_init(mbar0, 1); mbar_init(mbar0 + 8, 1); }

    // per-rank remote addresses
    const unsigned hloc = smem_u32(&hbuf[0][er][rank * 32 + ec]);
    unsigned rH[8], rM[8];
#pragma unroll
    for (int pr = 0; pr < 8; pr++) {
        rH[pr] = mapa_u32(hloc, pr);
        rM[pr] = mapa_u32(mbar0, pr);
    }

    cluster.sync();   // barriers + zeroed hbuf visible cluster-wide
    if (tid == 0) {
        mbar_expect_tx(mbar0 + 8, 8192);   // buf1: end-of-step-0 writes
        mbar_expect_tx(mbar0, 8192);       // buf0: end-of-step-1 writes
    }

    const float* xptr = xw + ((size_t)(b0 + er) * TLEN) * G4 + rank * 32 + ec;
    float* hptr = WRITE_SEQ
        ? out_seq + ((size_t)(b0 + er) * TLEN) * HID + rank * 32 + ec
        : nullptr;

    float c_state = 0.f;
    unsigned pp0 = 0, pp1 = 0;

    // preload xg for t=0
    float xg0 = xptr[0], xg1 = xptr[HID], xg2 = xptr[2 * HID], xg3 = xptr[3 * HID];
    xptr += G4;

    for (int t = 0; t < TLEN; t++) {
        const int p  = t & 1;
        const int nb = p ^ 1;

        if (t > 0) {
            if (p == 0) { mbar_wait_cluster(mbar0, pp0); pp0 ^= 1; }
            else        { mbar_wait_cluster(mbar0 + 8, pp1); pp1 ^= 1; }
            if (tid == 0) mbar_expect_tx(mbar0 + (unsigned)p * 8, 8192); // re-arm
        }

        // prefetch xg for t+1 (covered by phase1 + epilogue latency)
        float nx0 = 0.f, nx1 = 0.f, nx2 = 0.f, nx3 = 0.f;
        if (t + 1 < TLEN) {
            nx0 = xptr[0]; nx1 = xptr[HID]; nx2 = xptr[2 * HID]; nx3 = xptr[3 * HID];
            xptr += G4;
        }

        // ---- phase 1: partial gates = h @ U_slice (row-major, quad cols) ----
#pragma unroll
        for (int r = 0; r < 8; r++) {
            u64 a0 = 0ull, a1 = 0ull, a2 = 0ull, a3 = 0ull;
#pragma unroll
            for (int kq = 0; kq < 8; kq++) {
                float4 h4 = *(const float4*)&hbuf[p][r][kh * 32 + kq * 4];
                u64 hlo = pack2(h4.x, h4.y);
                u64 hhi = pack2(h4.z, h4.w);
                a0 = ffma2(hlo, u2[kq * 8 + 0], a0);
                a1 = ffma2(hlo, u2[kq * 8 + 1], a1);
                a2 = ffma2(hlo, u2[kq * 8 + 2], a2);
                a3 = ffma2(hlo, u2[kq * 8 + 3], a3);
                a0 = ffma2(hhi, u2[kq * 8 + 4], a0);
                a1 = ffma2(hhi, u2[kq * 8 + 5], a1);
                a2 = ffma2(hhi, u2[kq * 8 + 6], a2);
                a3 = ffma2(hhi, u2[kq * 8 + 7], a3);
            }
            float4 pv;
            pv.x = f2lo(a0) + f2hi(a0);
            pv.y = f2lo(a1) + f2hi(a1);
            pv.z = f2lo(a2) + f2hi(a2);
            pv.w = f2lo(a3) + f2hi(a3);
            *(float4*)&part[kh][r][4 * j] = pv;
        }
        __syncthreads();

        // ---- epilogue: reduce 8 k-groups, pointwise LSTM cell ----
        float v0 = xg0, v1 = xg1, v2 = xg2, v3 = xg3;
#pragma unroll
        for (int q = 0; q < 8; q++) {
            v0 += part[q][er][ec];
            v1 += part[q][er][32 + ec];
            v2 += part[q][er][64 + ec];
            v3 += part[q][er][96 + ec];
        }
        float ig = sigm_f(v0);
        float fg = sigm_f(v1);
        float gg = tanh_f(v2);
        float og = sigm_f(v3);
        c_state = fg * c_state + ig * gg;
        float hnew = og * tanh_f(c_state);

        if (WRITE_SEQ) { *hptr = hnew; hptr += HID; }

        if (t < TLEN - 1) {
            const unsigned hoff = (unsigned)(nb * 8 * HID) * 4u;
            const unsigned moff = (unsigned)nb * 8u;
#pragma unroll
            for (int pr = 0; pr < 8; pr++)
                st_async_f32(rH[pr] + hoff, hnew, rM[pr] + moff);
        } else if (!WRITE_SEQ) {
            out_last[(size_t)(b0 + er) * HID + rank * 32 + ec] = hnew;
        }

        xg0 = nx0; xg1 = nx1; xg2 = nx2; xg3 = nx3;
    }

    cluster.sync();   // don't exit with peer-targeted async traffic in flight
}

// ---------------------------------------------------------------------------
// Dense head: out[b] = relu( relu(h_last[b] @ Wd1 + bd1) @ Wd2 + bd2 )
// ---------------------------------------------------------------------------
__global__ __launch_bounds__(128)
void dense_head_kernel(const float* __restrict__ hlast,
                       const float* __restrict__ Wd1, const float* __restrict__ bd1,
                       const float* __restrict__ Wd2, const float* __restrict__ bd2,
                       float* __restrict__ out)
{
    __shared__ float hs[HID];
    __shared__ float red[4];
    const int b = blockIdx.x;
    const int j = threadIdx.x;

    hs[j]       = hlast[b * HID + j];
    hs[j + 128] = hlast[b * HID + j + 128];
    __syncthreads();

    float acc = bd1[j];
#pragma unroll 8
    for (int k = 0; k < HID; k++) acc = fmaf(hs[k], Wd1[k * 128 + j], acc);
    float hm = fmaxf(acc, 0.f) * Wd2[j];

#pragma unroll
    for (int off = 16; off > 0; off >>= 1)
        hm += __shfl_down_sync(0xffffffffu, hm, off);
    if ((j & 31) == 0) red[j >> 5] = hm;
    __syncthreads();
    if (j == 0) {
        float s = red[0] + red[1] + red[2] + red[3] + bd2[0];
        out[b] = fmaxf(s, 0.f);
    }
}

// ---------------------------------------------------------------------------
extern "C" void kernel_launch(void* const* d_in, const int* in_sizes, int n_in,
                              void* d_out, int out_size)
{
    const float* x   = (const float*)d_in[0];
    const float* W1  = (const float*)d_in[1];
    const float* U1  = (const float*)d_in[2];
    const float* b1  = (const float*)d_in[3];
    const float* W2  = (const float*)d_in[4];
    const float* U2  = (const float*)d_in[5];
    const float* b2  = (const float*)d_in[6];
    const float* Wd1 = (const float*)d_in[7];
    const float* bd1 = (const float*)d_in[8];
    const float* Wd2 = (const float*)d_in[9];
    const float* bd2 = (const float*)d_in[10];
    float* out = (float*)d_out;

    float *xw, *hseq, *hlast;
    cudaGetSymbolAddress((void**)&xw, g_xw);
    cudaGetSymbolAddress((void**)&hseq, g_hseq);
    cudaGetSymbolAddress((void**)&hlast, g_hlast);

    dim3 ggrid(G4 / 128, (BATCH * TLEN) / 128);

    gemm_bias_kernel<<<ggrid, 256>>>(x, W1, b1, xw, 128);
    lstm_layer<true><<<128, 256>>>(xw, U1, hseq, nullptr);
    gemm_bias_kernel<<<ggrid, 256>>>(hseq, W2, b2, xw, 256);
    lstm_layer<false><<<128, 256>>>(xw, U2, nullptr, hlast);
    dense_head_kernel<<<BATCH, 128>>>(hlast, Wd1, bd1, Wd2, bd2, out);
}

// round 5
// speedup vs baseline: 1.0996x; 1.0996x over previous
#include <cuda_runtime.h>
#include <cuda_bf16.h>
#include <cooperative_groups.h>
#include <cstdint>
#include <cstddef>

namespace cg = cooperative_groups;
using u64 = unsigned long long;

#define BATCH 128
#define TLEN  1024
#define HID   256
#define G4    1024  // 4*HID

// ---------------- packed f32x2 helpers ----------------
__device__ __forceinline__ u64 ffma2(u64 a, u64 b, u64 c) {
    u64 d;
    asm("fma.rn.f32x2 %0, %1, %2, %3;" : "=l"(d) : "l"(a), "l"(b), "l"(c));
    return d;
}
__device__ __forceinline__ u64 pack2(float lo, float hi) {
    u64 r;
    asm("mov.b64 %0, {%1, %2};" : "=l"(r) : "f"(lo), "f"(hi));
    return r;
}
__device__ __forceinline__ float f2lo(u64 v) { return __uint_as_float((unsigned)(v & 0xffffffffull)); }
__device__ __forceinline__ float f2hi(u64 v) { return __uint_as_float((unsigned)(v >> 32)); }

__device__ __forceinline__ float sigm_f(float x) {
    x = fminf(fmaxf(x, -30.f), 30.f);
    return __fdividef(1.f, 1.f + __expf(-x));
}
__device__ __forceinline__ float tanh_f(float x) {
    x = fminf(fmaxf(x, -15.f), 15.f);
    float e = __expf(2.f * x);
    return __fdividef(e - 1.f, e + 1.f);
}

// ---------------- cluster primitives ----------------
__device__ __forceinline__ unsigned smem_u32(const void* p) {
    return (unsigned)__cvta_generic_to_shared(p);
}
__device__ __forceinline__ unsigned mapa_u32(unsigned laddr, unsigned rank) {
    unsigned r;
    asm("mapa.shared::cluster.u32 %0, %1, %2;" : "=r"(r) : "r"(laddr), "r"(rank));
    return r;
}
// 1KB smem->peer-smem bulk copy, completion counted on the peer's mbarrier.
__device__ __forceinline__ void bulk_s2cluster(unsigned dst, unsigned src,
                                               unsigned bytes, unsigned rmbar) {
    asm volatile(
        "cp.async.bulk.shared::cluster.shared::cta.mbarrier::complete_tx::bytes "
        "[%0], [%1], %2, [%3];"
        :: "r"(dst), "r"(src), "r"(bytes), "r"(rmbar) : "memory");
}
__device__ __forceinline__ void fence_proxy_async_cta() {
    asm volatile("fence.proxy.async.shared::cta;" ::: "memory");
}
__device__ __forceinline__ void mbar_init(unsigned mbar, unsigned cnt) {
    asm volatile("mbarrier.init.shared.b64 [%0], %1;" :: "r"(mbar), "r"(cnt) : "memory");
}
__device__ __forceinline__ void mbar_expect_tx(unsigned mbar, unsigned bytes) {
    asm volatile("mbarrier.arrive.expect_tx.shared.b64 _, [%0], %1;"
                 :: "r"(mbar), "r"(bytes) : "memory");
}
__device__ __forceinline__ void mbar_wait_cluster(unsigned mbar, unsigned parity) {
    asm volatile(
        "{\n\t"
        ".reg .pred P;\n"
        "LWAIT_%=:\n\t"
        "mbarrier.try_wait.parity.acquire.cluster.shared::cta.b64 P, [%0], %1, 0x989680;\n\t"
        "@P bra LDONE_%=;\n\t"
        "bra LWAIT_%=;\n"
        "LDONE_%=:\n\t"
        "}"
        :: "r"(mbar), "r"(parity) : "memory");
}

// ---------------- scratch (static device globals) ----------------
__device__ float g_xw[(size_t)BATCH * TLEN * G4];     // 512 MB, reused by both layers
__device__ float g_hseq[(size_t)BATCH * TLEN * HID];  // 128 MB
__device__ float g_hlast[BATCH * HID];

// ---------------------------------------------------------------------------
// GEMM: C[M,1024] = A[M,K] @ B[K,1024] + bias, M=131072, K in {128,256}
// 128x128 tile, BK=16, 256 threads, 8x8 micro-tile, FFMA2, double-buffered.
// ---------------------------------------------------------------------------
__global__ __launch_bounds__(256, 2)
void gemm_bias_kernel(const float* __restrict__ A, const float* __restrict__ B,
                      const float* __restrict__ bias, float* __restrict__ C, int K)
{
    const int N = G4;
    __shared__ float As[2][16][128];
    __shared__ float Bs[2][16][128];

    const int tid = threadIdx.x;
    const int n0  = blockIdx.x * 128;
    const size_t m0 = (size_t)blockIdx.y * 128;
    const int tn = tid & 15;
    const int tm = tid >> 4;

    float4 av[2], bv[2];
    const int NKB = K >> 4;

    auto ldg_tiles = [&](int k0) {
#pragma unroll
        for (int i = 0; i < 2; i++) {
            int idx = tid + i * 256;
            int ar = idx >> 2, kq = idx & 3;
            av[i] = *(const float4*)&A[(m0 + ar) * K + k0 + kq * 4];
            int kr = idx >> 5, nq = idx & 31;
            bv[i] = *(const float4*)&B[(size_t)(k0 + kr) * N + n0 + nq * 4];
        }
    };
    auto sts_tiles = [&](int buf) {
#pragma unroll
        for (int i = 0; i < 2; i++) {
            int idx = tid + i * 256;
            int ar = idx >> 2, kq = idx & 3;
            As[buf][kq * 4 + 0][ar] = av[i].x;
            As[buf][kq * 4 + 1][ar] = av[i].y;
            As[buf][kq * 4 + 2][ar] = av[i].z;
            As[buf][kq * 4 + 3][ar] = av[i].w;
            int kr = idx >> 5, nq = idx & 31;
            *(float4*)&Bs[buf][kr][nq * 4] = bv[i];
        }
    };

    u64 acc[8][4];
#pragma unroll
    for (int m = 0; m < 8; m++)
#pragma unroll
        for (int j = 0; j < 4; j++) acc[m][j] = 0ull;

    ldg_tiles(0);
    sts_tiles(0);
    __syncthreads();

    for (int kb = 0; kb < NKB; kb++) {
        if (kb + 1 < NKB) ldg_tiles((kb + 1) << 4);
        const int buf = kb & 1;
#pragma unroll
        for (int k = 0; k < 16; k++) {
            float4 a0 = *(const float4*)&As[buf][k][tm * 8];
            float4 a1 = *(const float4*)&As[buf][k][tm * 8 + 4];
            u64 b0v = *(const u64*)&Bs[buf][k][2 * tn];
            u64 b1v = *(const u64*)&Bs[buf][k][2 * tn + 32];
            u64 b2v = *(const u64*)&Bs[buf][k][2 * tn + 64];
            u64 b3v = *(const u64*)&Bs[buf][k][2 * tn + 96];
            float aa[8] = {a0.x, a0.y, a0.z, a0.w, a1.x, a1.y, a1.z, a1.w};
#pragma unroll
            for (int m = 0; m < 8; m++) {
                u64 am = pack2(aa[m], aa[m]);
                acc[m][0] = ffma2(am, b0v, acc[m][0]);
                acc[m][1] = ffma2(am, b1v, acc[m][1]);
                acc[m][2] = ffma2(am, b2v, acc[m][2]);
                acc[m][3] = ffma2(am, b3v, acc[m][3]);
            }
        }
        if (kb + 1 < NKB) sts_tiles(buf ^ 1);
        __syncthreads();
    }

    float bias_r[8];
#pragma unroll
    for (int j = 0; j < 4; j++) {
        bias_r[2 * j]     = bias[n0 + 2 * tn + 32 * j];
        bias_r[2 * j + 1] = bias[n0 + 2 * tn + 32 * j + 1];
    }

#pragma unroll
    for (int m = 0; m < 8; m++) {
        size_t row = m0 + tm * 8 + m;
        float* cp = &C[row * N + n0];
#pragma unroll
        for (int j = 0; j < 4; j++) {
            float2 v;
            v.x = f2lo(acc[m][j]) + bias_r[2 * j];
            v.y = f2hi(acc[m][j]) + bias_r[2 * j + 1];
            *(float2*)&cp[2 * tn + 32 * j] = v;
        }
    }
}

// ---------------------------------------------------------------------------
// Persistent-cluster LSTM recurrence. Exchange = 7 bulk DSMEM copies per CTA
// per step (1KB each), tx-counted on the receiver's mbarrier (7 tx/step vs
// 2048 scalar st.async tx previously).
// Grid: 128 CTAs = 16 clusters x 8 CTAs, 256 threads.
// h layout: hbuf[2][ownerRank][row][32]  (rank-major 1KB blocks).
// Phase-1 (R3 structure): gcA=tid&63 (+64 for B), kh=tid>>6 owns 64-wide
// k-slice; batched float4 broadcast loads of h (MLP=8) then FFMA2.
// Epilogue: er=tid>>5 (row), ec=tid&31 (col in own rank's 32).
// ---------------------------------------------------------------------------
template <bool WRITE_SEQ>
__global__ void __cluster_dims__(8, 1, 1) __launch_bounds__(256, 1)
lstm_layer(const float* __restrict__ xw, const float* __restrict__ U,
           float* __restrict__ out_seq, float* __restrict__ out_last)
{
    __shared__ __align__(16) float hbuf[2][8][8][32]; // 16 KB: [buf][rank][row][col]
    __shared__ float part[4][8][128];                 // 16 KB, k-group partials
    __shared__ __align__(8) u64 mbars[2];             // tx barriers per buffer

    cg::cluster_group cluster = cg::this_cluster();
    const int tid  = threadIdx.x;
    const int rank = (int)cluster.block_rank();
    const int cid  = blockIdx.x >> 3;
    const int b0   = cid * 8;

    // phase-1 roles (R3 mapping)
    const int gcA = tid & 63;
    const int gcB = gcA + 64;
    const int kh  = tid >> 6;                 // k block [kh*64, kh*64+64)
    const int colA = (gcA >> 5) * 256 + rank * 32 + (gcA & 31);
    const int colB = (gcB >> 5) * 256 + rank * 32 + (gcB & 31);

    // epilogue roles
    const int er = tid >> 5;                  // batch row within cluster
    const int ec = tid & 31;                  // h column within rank's 32

    // U slice in registers: 32 k-pairs x 2 columns
    u64 u2a[32], u2b[32];
#pragma unroll
    for (int kp = 0; kp < 32; kp++) {
        int k = kh * 64 + 2 * kp;
        u2a[kp] = pack2(U[(size_t)k * G4 + colA], U[(size_t)(k + 1) * G4 + colA]);
        u2b[kp] = pack2(U[(size_t)k * G4 + colB], U[(size_t)(k + 1) * G4 + colB]);
    }

    // init smem
    for (int i = tid; i < 2 * 8 * 8 * 32; i += 256) ((float*)hbuf)[i] = 0.f;
    const unsigned mbar0 = smem_u32(&mbars[0]);
    if (tid == 0) { mbar_init(mbar0, 1); mbar_init(mbar0 + 8, 1); }

    // bulk-copy source (own rank's block) per buffer, and per-peer dst/mbar
    const unsigned src0 = smem_u32(&hbuf[0][rank][0][0]);
    const unsigned src1 = smem_u32(&hbuf[1][rank][0][0]);
    unsigned rD0[8], rD1[8], rMB[8];
#pragma unroll
    for (int pr = 0; pr < 8; pr++) {
        rD0[pr] = mapa_u32(src0, pr);
        rD1[pr] = mapa_u32(src1, pr);
        rMB[pr] = mapa_u32(mbar0, pr);
    }

    cluster.sync();   // barriers + zeroed hbuf visible cluster-wide
    if (tid == 0) {
        mbar_expect_tx(mbar0 + 8, 7 * 1024);   // buf1: end-of-step-0 copies
        mbar_expect_tx(mbar0, 7 * 1024);       // buf0: end-of-step-1 copies
    }

    const float* xptr = xw + ((size_t)(b0 + er) * TLEN) * G4 + rank * 32 + ec;
    float* hptr = WRITE_SEQ
        ? out_seq + ((size_t)(b0 + er) * TLEN) * HID + rank * 32 + ec
        : nullptr;

    float c_state = 0.f;
    unsigned pp0 = 0, pp1 = 0;

    for (int t = 0; t < TLEN; t++) {
        const int p  = t & 1;
        const int nb = p ^ 1;

        // prefetch xw gate inputs before the wait (hide LDG under the stall)
        float xg0 = xptr[0];
        float xg1 = xptr[HID];
        float xg2 = xptr[2 * HID];
        float xg3 = xptr[3 * HID];
        xptr += G4;

        if (t > 0) {
            if (p == 0) { mbar_wait_cluster(mbar0, pp0); pp0 ^= 1; }
            else        { mbar_wait_cluster(mbar0 + 8, pp1); pp1 ^= 1; }
            if (tid == 0) mbar_expect_tx(mbar0 + (unsigned)p * 8, 7 * 1024); // re-arm
        }

        // ---- phase 1: partial gates = h @ U_slice (R3 batched-load form) ----
        u64 accA[8], accB[8];
#pragma unroll
        for (int r = 0; r < 8; r++) { accA[r] = 0ull; accB[r] = 0ull; }

#pragma unroll
        for (int kq = 0; kq < 16; kq++) {
            const int kg  = kh * 64 + kq * 4;       // global k
            const int blk = kg >> 5;                // owner rank of this k
            const int off = kg & 31;
            float4 h4[8];
#pragma unroll
            for (int r = 0; r < 8; r++) h4[r] = *(const float4*)&hbuf[p][blk][r][off];
            u64 ua0 = u2a[2 * kq], ua1 = u2a[2 * kq + 1];
            u64 ub0 = u2b[2 * kq], ub1 = u2b[2 * kq + 1];
#pragma unroll
            for (int r = 0; r < 8; r++) {
                u64 hlo = pack2(h4[r].x, h4[r].y);
                u64 hhi = pack2(h4[r].z, h4[r].w);
                accA[r] = ffma2(hlo, ua0, accA[r]);
                accA[r] = ffma2(hhi, ua1, accA[r]);
                accB[r] = ffma2(hlo, ub0, accB[r]);
                accB[r] = ffma2(hhi, ub1, accB[r]);
            }
        }
#pragma unroll
        for (int r = 0; r < 8; r++) {
            part[kh][r][gcA] = f2lo(accA[r]) + f2hi(accA[r]);
            part[kh][r][gcB] = f2lo(accB[r]) + f2hi(accB[r]);
        }
        __syncthreads();

        // ---- epilogue ----
        float v0 = xg0, v1 = xg1, v2 = xg2, v3 = xg3;
#pragma unroll
        for (int q = 0; q < 4; q++) {
            v0 += part[q][er][ec];
            v1 += part[q][er][32 + ec];
            v2 += part[q][er][64 + ec];
            v3 += part[q][er][96 + ec];
        }
        float ig = sigm_f(v0);
        float fg = sigm_f(v1);
        float gg = tanh_f(v2);
        float og = sigm_f(v3);
        c_state = fg * c_state + ig * gg;
        float hnew = og * tanh_f(c_state);

        if (WRITE_SEQ) { *hptr = hnew; hptr += HID; }

        if (t < TLEN - 1) {
            // write own block locally, then push it to the 7 peers in bulk
            hbuf[nb][rank][er][ec] = hnew;
            __syncthreads();
            if (tid == 0) {
                fence_proxy_async_cta();
                const unsigned src  = nb ? src1 : src0;
                const unsigned* rD  = nb ? rD1 : rD0;
                const unsigned moff = (unsigned)nb * 8u;
#pragma unroll
                for (int pr = 0; pr < 8; pr++) {
                    if (pr != rank)
                        bulk_s2cluster(rD[pr], src, 1024u, rMB[pr] + moff);
                }
            }
        } else if (!WRITE_SEQ) {
            out_last[(size_t)(b0 + er) * HID + rank * 32 + ec] = hnew;
        }
    }

    cluster.sync();   // don't exit with peer-targeted async traffic in flight
}

// ---------------------------------------------------------------------------
// Dense head: out[b] = relu( relu(h_last[b] @ Wd1 + bd1) @ Wd2 + bd2 )
// ---------------------------------------------------------------------------
__global__ __launch_bounds__(128)
void dense_head_kernel(const float* __restrict__ hlast,
                       const float* __restrict__ Wd1, const float* __restrict__ bd1,
                       const float* __restrict__ Wd2, const float* __restrict__ bd2,
                       float* __restrict__ out)
{
    __shared__ float hs[HID];
    __shared__ float red[4];
    const int b = blockIdx.x;
    const int j = threadIdx.x;

    hs[j]       = hlast[b * HID + j];
    hs[j + 128] = hlast[b * HID + j + 128];
    __syncthreads();

    float acc = bd1[j];
#pragma unroll 8
    for (int k = 0; k < HID; k++) acc = fmaf(hs[k], Wd1[k * 128 + j], acc);
    float hm = fmaxf(acc, 0.f) * Wd2[j];

#pragma unroll
    for (int off = 16; off > 0; off >>= 1)
        hm += __shfl_down_sync(0xffffffffu, hm, off);
    if ((j & 31) == 0) red[j >> 5] = hm;
    __syncthreads();
    if (j == 0) {
        float s = red[0] + red[1] + red[2] + red[3] + bd2[0];
        out[b] = fmaxf(s, 0.f);
    }
}

// ---------------------------------------------------------------------------
extern "C" void kernel_launch(void* const* d_in, const int* in_sizes, int n_in,
                              void* d_out, int out_size)
{
    const float* x   = (const float*)d_in[0];
    const float* W1  = (const float*)d_in[1];
    const float* U1  = (const float*)d_in[2];
    const float* b1  = (const float*)d_in[3];
    const float* W2  = (const float*)d_in[4];
    const float* U2  = (const float*)d_in[5];
    const float* b2  = (const float*)d_in[6];
    const float* Wd1 = (const float*)d_in[7];
    const float* bd1 = (const float*)d_in[8];
    const float* Wd2 = (const float*)d_in[9];
    const float* bd2 = (const float*)d_in[10];
    float* out = (float*)d_out;

    float *xw, *hseq, *hlast;
    cudaGetSymbolAddress((void**)&xw, g_xw);
    cudaGetSymbolAddress((void**)&hseq, g_hseq);
    cudaGetSymbolAddress((void**)&hlast, g_hlast);

    dim3 ggrid(G4 / 128, (BATCH * TLEN) / 128);

    gemm_bias_kernel<<<ggrid, 256>>>(x, W1, b1, xw, 128);
    lstm_layer<true><<<128, 256>>>(xw, U1, hseq, nullptr);
    gemm_bias_kernel<<<ggrid, 256>>>(hseq, W2, b2, xw, 256);
    lstm_layer<false><<<128, 256>>>(xw, U2, nullptr, hlast);
    dense_head_kernel<<<BATCH, 128>>>(hlast, Wd1, bd1, Wd2, bd2, out);
}

// round 6
// speedup vs baseline: 1.1137x; 1.0128x over previous
#include <cuda_runtime.h>
#include <cuda_bf16.h>
#include <cooperative_groups.h>
#include <cstdint>
#include <cstddef>

namespace cg = cooperative_groups;
using u64 = unsigned long long;

#define BATCH 128
#define TLEN  1024
#define HID   256
#define G4    1024  // 4*HID

// ---------------- packed f32x2 helpers ----------------
__device__ __forceinline__ u64 ffma2(u64 a, u64 b, u64 c) {
    u64 d;
    asm("fma.rn.f32x2 %0, %1, %2, %3;" : "=l"(d) : "l"(a), "l"(b), "l"(c));
    return d;
}
__device__ __forceinline__ u64 pack2(float lo, float hi) {
    u64 r;
    asm("mov.b64 %0, {%1, %2};" : "=l"(r) : "f"(lo), "f"(hi));
    return r;
}
__device__ __forceinline__ float f2lo(u64 v) { return __uint_as_float((unsigned)(v & 0xffffffffull)); }
__device__ __forceinline__ float f2hi(u64 v) { return __uint_as_float((unsigned)(v >> 32)); }

__device__ __forceinline__ float sigm_f(float x) {
    x = fminf(fmaxf(x, -30.f), 30.f);
    return __fdividef(1.f, 1.f + __expf(-x));
}
__device__ __forceinline__ float tanh_f(float x) {
    x = fminf(fmaxf(x, -15.f), 15.f);
    float e = __expf(2.f * x);
    return __fdividef(e - 1.f, e + 1.f);
}

// ---------------- cluster async-store primitives ----------------
__device__ __forceinline__ unsigned smem_u32(const void* p) {
    return (unsigned)__cvta_generic_to_shared(p);
}
__device__ __forceinline__ unsigned mapa_u32(unsigned laddr, unsigned rank) {
    unsigned r;
    asm("mapa.shared::cluster.u32 %0, %1, %2;" : "=r"(r) : "r"(laddr), "r"(rank));
    return r;
}
__device__ __forceinline__ void st_async_f32(unsigned raddr, float v, unsigned rmbar) {
    asm volatile("st.async.shared::cluster.mbarrier::complete_tx::bytes.b32 [%0], %1, [%2];"
                 :: "r"(raddr), "r"(__float_as_uint(v)), "r"(rmbar) : "memory");
}
__device__ __forceinline__ void mbar_init(unsigned mbar, unsigned cnt) {
    asm volatile("mbarrier.init.shared.b64 [%0], %1;" :: "r"(mbar), "r"(cnt) : "memory");
}
__device__ __forceinline__ void mbar_expect_tx(unsigned mbar, unsigned bytes) {
    asm volatile("mbarrier.arrive.expect_tx.shared.b64 _, [%0], %1;"
                 :: "r"(mbar), "r"(bytes) : "memory");
}
__device__ __forceinline__ void mbar_wait_cluster(unsigned mbar, unsigned parity) {
    asm volatile(
        "{\n\t"
        ".reg .pred P;\n"
        "LWAIT_%=:\n\t"
        "mbarrier.try_wait.parity.acquire.cluster.shared::cta.b64 P, [%0], %1, 0x989680;\n\t"
        "@P bra LDONE_%=;\n\t"
        "bra LWAIT_%=;\n"
        "LDONE_%=:\n\t"
        "}"
        :: "r"(mbar), "r"(parity) : "memory");
}

// ---------------- scratch (static device globals) ----------------
__device__ float g_xw[(size_t)BATCH * TLEN * G4];     // 512 MB, reused by both layers
__device__ float g_hseq[(size_t)BATCH * TLEN * HID];  // 128 MB
__device__ float g_hlast[BATCH * HID];

// ---------------------------------------------------------------------------
// GEMM: C[M,1024] = A[M,K] @ B[K,1024] + bias, M=131072, K in {128,256}
// 128x128 tile, BK=16, 256 threads, 8x8 micro-tile, FFMA2, double-buffered.
// ---------------------------------------------------------------------------
__global__ __launch_bounds__(256, 2)
void gemm_bias_kernel(const float* __restrict__ A, const float* __restrict__ B,
                      const float* __restrict__ bias, float* __restrict__ C, int K)
{
    const int N = G4;
    __shared__ float As[2][16][128];
    __shared__ float Bs[2][16][128];

    const int tid = threadIdx.x;
    const int n0  = blockIdx.x * 128;
    const size_t m0 = (size_t)blockIdx.y * 128;
    const int tn = tid & 15;
    const int tm = tid >> 4;

    float4 av[2], bv[2];
    const int NKB = K >> 4;

    auto ldg_tiles = [&](int k0) {
#pragma unroll
        for (int i = 0; i < 2; i++) {
            int idx = tid + i * 256;
            int ar = idx >> 2, kq = idx & 3;
            av[i] = *(const float4*)&A[(m0 + ar) * K + k0 + kq * 4];
            int kr = idx >> 5, nq = idx & 31;
            bv[i] = *(const float4*)&B[(size_t)(k0 + kr) * N + n0 + nq * 4];
        }
    };
    auto sts_tiles = [&](int buf) {
#pragma unroll
        for (int i = 0; i < 2; i++) {
            int idx = tid + i * 256;
            int ar = idx >> 2, kq = idx & 3;
            As[buf][kq * 4 + 0][ar] = av[i].x;
            As[buf][kq * 4 + 1][ar] = av[i].y;
            As[buf][kq * 4 + 2][ar] = av[i].z;
            As[buf][kq * 4 + 3][ar] = av[i].w;
            int kr = idx >> 5, nq = idx & 31;
            *(float4*)&Bs[buf][kr][nq * 4] = bv[i];
        }
    };

    u64 acc[8][4];
#pragma unroll
    for (int m = 0; m < 8; m++)
#pragma unroll
        for (int j = 0; j < 4; j++) acc[m][j] = 0ull;

    ldg_tiles(0);
    sts_tiles(0);
    __syncthreads();

    for (int kb = 0; kb < NKB; kb++) {
        if (kb + 1 < NKB) ldg_tiles((kb + 1) << 4);
        const int buf = kb & 1;
#pragma unroll
        for (int k = 0; k < 16; k++) {
            float4 a0 = *(const float4*)&As[buf][k][tm * 8];
            float4 a1 = *(const float4*)&As[buf][k][tm * 8 + 4];
            u64 b0v = *(const u64*)&Bs[buf][k][2 * tn];
            u64 b1v = *(const u64*)&Bs[buf][k][2 * tn + 32];
            u64 b2v = *(const u64*)&Bs[buf][k][2 * tn + 64];
            u64 b3v = *(const u64*)&Bs[buf][k][2 * tn + 96];
            float aa[8] = {a0.x, a0.y, a0.z, a0.w, a1.x, a1.y, a1.z, a1.w};
#pragma unroll
            for (int m = 0; m < 8; m++) {
                u64 am = pack2(aa[m], aa[m]);
                acc[m][0] = ffma2(am, b0v, acc[m][0]);
                acc[m][1] = ffma2(am, b1v, acc[m][1]);
                acc[m][2] = ffma2(am, b2v, acc[m][2]);
                acc[m][3] = ffma2(am, b3v, acc[m][3]);
            }
        }
        if (kb + 1 < NKB) sts_tiles(buf ^ 1);
        __syncthreads();
    }

    float bias_r[8];
#pragma unroll
    for (int j = 0; j < 4; j++) {
        bias_r[2 * j]     = bias[n0 + 2 * tn + 32 * j];
        bias_r[2 * j + 1] = bias[n0 + 2 * tn + 32 * j + 1];
    }

#pragma unroll
    for (int m = 0; m < 8; m++) {
        size_t row = m0 + tm * 8 + m;
        float* cp = &C[row * N + n0];
#pragma unroll
        for (int j = 0; j < 4; j++) {
            float2 v;
            v.x = f2lo(acc[m][j]) + bias_r[2 * j];
            v.y = f2hi(acc[m][j]) + bias_r[2 * j + 1];
            *(float2*)&cp[2 * tn + 32 * j] = v;
        }
    }
}

// ---------------------------------------------------------------------------
// Persistent-cluster LSTM recurrence, st.async exchange (R3 champion layout).
// Grid: 128 CTAs = 16 clusters x 8 CTAs, 256 threads.
// Cluster cid owns batch rows [8cid, 8cid+8). CTA rank owns 128 gate columns
//   col(gc) = (gc>>5)*256 + rank*32 + (gc&31), gc in [0,128), U slice in regs.
// CHANGE vs R3: phase-1 h operands loaded directly as ulonglong2 (two packed
// f32x2 words) — zero pack/MOV ALU ops feeding the FFMA2s.
// ---------------------------------------------------------------------------
template <bool WRITE_SEQ>
__global__ void __cluster_dims__(8, 1, 1) __launch_bounds__(256, 1)
lstm_layer(const float* __restrict__ xw, const float* __restrict__ U,
           float* __restrict__ out_seq, float* __restrict__ out_last)
{
    __shared__ __align__(16) float hbuf[2][8][HID];   // 16 KB, dbl-buffered h
    __shared__ float part[4][8][128];                 // 16 KB, k-group partials
    __shared__ __align__(8) u64 mbars[2];             // tx barriers per buffer

    cg::cluster_group cluster = cg::this_cluster();
    const int tid  = threadIdx.x;
    const int rank = (int)cluster.block_rank();
    const int cid  = blockIdx.x >> 3;
    const int b0   = cid * 8;

    // phase-1 roles
    const int gcA = tid & 63;
    const int gcB = gcA + 64;
    const int kh  = tid >> 6;                 // k block [kh*64, kh*64+64)
    const int colA = (gcA >> 5) * 256 + rank * 32 + (gcA & 31);
    const int colB = (gcB >> 5) * 256 + rank * 32 + (gcB & 31);

    // epilogue roles
    const int er = tid >> 5;                  // batch row within cluster
    const int ec = tid & 31;                  // h column within rank's 32

    // U slice in registers: 32 k-pairs x 2 columns
    u64 u2a[32], u2b[32];
#pragma unroll
    for (int kp = 0; kp < 32; kp++) {
        int k = kh * 64 + 2 * kp;
        u2a[kp] = pack2(U[(size_t)k * G4 + colA], U[(size_t)(k + 1) * G4 + colA]);
        u2b[kp] = pack2(U[(size_t)k * G4 + colB], U[(size_t)(k + 1) * G4 + colB]);
    }

    // init smem
    for (int i = tid; i < 2 * 8 * HID; i += 256) ((float*)hbuf)[i] = 0.f;
    const unsigned mbar0 = smem_u32(&mbars[0]);
    if (tid == 0) { mbar_init(mbar0, 1); mbar_init(mbar0 + 8, 1); }

    // precompute per-rank remote addresses (byte offsets within peer smem)
    const unsigned hloc = smem_u32(&hbuf[0][er][rank * 32 + ec]);
    unsigned rH[8], rM[8];
#pragma unroll
    for (int pr = 0; pr < 8; pr++) {
        rH[pr] = mapa_u32(hloc, pr);
        rM[pr] = mapa_u32(mbar0, pr);
    }

    cluster.sync();   // barriers + zeroed hbuf visible cluster-wide
    if (tid == 0) {
        mbar_expect_tx(mbar0 + 8, 8192);   // buf1: end-of-step-0 writes
        mbar_expect_tx(mbar0, 8192);       // buf0: end-of-step-1 writes
    }

    const float* xptr = xw + ((size_t)(b0 + er) * TLEN) * G4 + rank * 32 + ec;
    float* hptr = WRITE_SEQ
        ? out_seq + ((size_t)(b0 + er) * TLEN) * HID + rank * 32 + ec
        : nullptr;

    float c_state = 0.f;
    unsigned pp0 = 0, pp1 = 0;

    for (int t = 0; t < TLEN; t++) {
        const int p  = t & 1;
        const int nb = p ^ 1;

        // prefetch xw gate inputs before the wait (hide LDG under the stall)
        float xg0 = xptr[0];
        float xg1 = xptr[HID];
        float xg2 = xptr[2 * HID];
        float xg3 = xptr[3 * HID];
        xptr += G4;

        if (t > 0) {
            if (p == 0) { mbar_wait_cluster(mbar0, pp0); pp0 ^= 1; }
            else        { mbar_wait_cluster(mbar0 + 8, pp1); pp1 ^= 1; }
            if (tid == 0) mbar_expect_tx(mbar0 + (unsigned)p * 8, 8192); // re-arm
        }

        // ---- phase 1: partial gates = h @ U_slice ----
        // h loaded as ulonglong2: .x = packed(h[k],h[k+1]), .y = packed(h[k+2],h[k+3])
        u64 accA[8], accB[8];
#pragma unroll
        for (int r = 0; r < 8; r++) { accA[r] = 0ull; accB[r] = 0ull; }

#pragma unroll
        for (int kq = 0; kq < 16; kq++) {
            const int k = kh * 64 + kq * 4;
            ulonglong2 h2[8];
#pragma unroll
            for (int r = 0; r < 8; r++)
                h2[r] = *(const ulonglong2*)&hbuf[p][r][k];
            u64 ua0 = u2a[2 * kq], ua1 = u2a[2 * kq + 1];
            u64 ub0 = u2b[2 * kq], ub1 = u2b[2 * kq + 1];
#pragma unroll
            for (int r = 0; r < 8; r++) {
                accA[r] = ffma2(h2[r].x, ua0, accA[r]);
                accA[r] = ffma2(h2[r].y, ua1, accA[r]);
                accB[r] = ffma2(h2[r].x, ub0, accB[r]);
                accB[r] = ffma2(h2[r].y, ub1, accB[r]);
            }
        }
#pragma unroll
        for (int r = 0; r < 8; r++) {
            part[kh][r][gcA] = f2lo(accA[r]) + f2hi(accA[r]);
            part[kh][r][gcB] = f2lo(accB[r]) + f2hi(accB[r]);
        }
        __syncthreads();

        // ---- epilogue ----
        float v0 = xg0, v1 = xg1, v2 = xg2, v3 = xg3;
#pragma unroll
        for (int q = 0; q < 4; q++) {
            v0 += part[q][er][ec];
            v1 += part[q][er][32 + ec];
            v2 += part[q][er][64 + ec];
            v3 += part[q][er][96 + ec];
        }
        float ig = sigm_f(v0);
        float fg = sigm_f(v1);
        float gg = tanh_f(v2);
        float og = sigm_f(v3);
        c_state = fg * c_state + ig * gg;
        float hnew = og * tanh_f(c_state);

        if (WRITE_SEQ) { *hptr = hnew; hptr += HID; }

        if (t < TLEN - 1) {
            const unsigned hoff = (unsigned)(nb * 8 * HID) * 4u;
            const unsigned moff = (unsigned)nb * 8u;
#pragma unroll
            for (int pr = 0; pr < 8; pr++)
                st_async_f32(rH[pr] + hoff, hnew, rM[pr] + moff);
        } else if (!WRITE_SEQ) {
            out_last[(size_t)(b0 + er) * HID + rank * 32 + ec] = hnew;
        }
    }

    cluster.sync();   // don't exit with peer-targeted async traffic in flight
}

// ---------------------------------------------------------------------------
// Dense head: out[b] = relu( relu(h_last[b] @ Wd1 + bd1) @ Wd2 + bd2 )
// ---------------------------------------------------------------------------
__global__ __launch_bounds__(128)
void dense_head_kernel(const float* __restrict__ hlast,
                       const float* __restrict__ Wd1, const float* __restrict__ bd1,
                       const float* __restrict__ Wd2, const float* __restrict__ bd2,
                       float* __restrict__ out)
{
    __shared__ float hs[HID];
    __shared__ float red[4];
    const int b = blockIdx.x;
    const int j = threadIdx.x;

    hs[j]       = hlast[b * HID + j];
    hs[j + 128] = hlast[b * HID + j + 128];
    __syncthreads();

    float acc = bd1[j];
#pragma unroll 8
    for (int k = 0; k < HID; k++) acc = fmaf(hs[k], Wd1[k * 128 + j], acc);
    float hm = fmaxf(acc, 0.f) * Wd2[j];

#pragma unroll
    for (int off = 16; off > 0; off >>= 1)
        hm += __shfl_down_sync(0xffffffffu, hm, off);
    if ((j & 31) == 0) red[j >> 5] = hm;
    __syncthreads();
    if (j == 0) {
        float s = red[0] + red[1] + red[2] + red[3] + bd2[0];
        out[b] = fmaxf(s, 0.f);
    }
}

// ---------------------------------------------------------------------------
extern "C" void kernel_launch(void* const* d_in, const int* in_sizes, int n_in,
                              void* d_out, int out_size)
{
    const float* x   = (const float*)d_in[0];
    const float* W1  = (const float*)d_in[1];
    const float* U1  = (const float*)d_in[2];
    const float* b1  = (const float*)d_in[3];
    const float* W2  = (const float*)d_in[4];
    const float* U2  = (const float*)d_in[5];
    const float* b2  = (const float*)d_in[6];
    const float* Wd1 = (const float*)d_in[7];
    const float* bd1 = (const float*)d_in[8];
    const float* Wd2 = (const float*)d_in[9];
    const float* bd2 = (const float*)d_in[10];
    float* out = (float*)d_out;

    float *xw, *hseq, *hlast;
    cudaGetSymbolAddress((void**)&xw, g_xw);
    cudaGetSymbolAddress((void**)&hseq, g_hseq);
    cudaGetSymbolAddress((void**)&hlast, g_hlast);

    dim3 ggrid(G4 / 128, (BATCH * TLEN) / 128);

    gemm_bias_kernel<<<ggrid, 256>>>(x, W1, b1, xw, 128);
    lstm_layer<true><<<128, 256>>>(xw, U1, hseq, nullptr);
    gemm_bias_kernel<<<ggrid, 256>>>(hseq, W2, b2, xw, 256);
    lstm_layer<false><<<128, 256>>>(xw, U2, nullptr, hlast);
    dense_head_kernel<<<BATCH, 128>>>(hlast, Wd1, bd1, Wd2, bd2, out);
}

// round 7
// speedup vs baseline: 1.2561x; 1.1279x over previous
#include <cuda_runtime.h>
#include <cuda_bf16.h>
#include <cooperative_groups.h>
#include <cstdint>
#include <cstddef>

namespace cg = cooperative_groups;
using u64 = unsigned long long;

#define BATCH 128
#define TLEN  1024
#define HID   256
#define G4    1024  // 4*HID

// ---------------- packed f32x2 helpers ----------------
__device__ __forceinline__ u64 ffma2(u64 a, u64 b, u64 c) {
    u64 d;
    asm("fma.rn.f32x2 %0, %1, %2, %3;" : "=l"(d) : "l"(a), "l"(b), "l"(c));
    return d;
}
__device__ __forceinline__ u64 pack2(float lo, float hi) {
    u64 r;
    asm("mov.b64 %0, {%1, %2};" : "=l"(r) : "f"(lo), "f"(hi));
    return r;
}
__device__ __forceinline__ float f2lo(u64 v) { return __uint_as_float((unsigned)(v & 0xffffffffull)); }
__device__ __forceinline__ float f2hi(u64 v) { return __uint_as_float((unsigned)(v >> 32)); }

__device__ __forceinline__ float sigm_f(float x) {
    x = fminf(fmaxf(x, -30.f), 30.f);
    return __fdividef(1.f, 1.f + __expf(-x));
}
__device__ __forceinline__ float tanh_f(float x) {
    x = fminf(fmaxf(x, -15.f), 15.f);
    float e = __expf(2.f * x);
    return __fdividef(e - 1.f, e + 1.f);
}

// ---------------- cluster async-store primitives ----------------
__device__ __forceinline__ unsigned smem_u32(const void* p) {
    return (unsigned)__cvta_generic_to_shared(p);
}
__device__ __forceinline__ unsigned mapa_u32(unsigned laddr, unsigned rank) {
    unsigned r;
    asm("mapa.shared::cluster.u32 %0, %1, %2;" : "=r"(r) : "r"(laddr), "r"(rank));
    return r;
}
__device__ __forceinline__ void st_async_f32(unsigned raddr, float v, unsigned rmbar) {
    asm volatile("st.async.shared::cluster.mbarrier::complete_tx::bytes.b32 [%0], %1, [%2];"
                 :: "r"(raddr), "r"(__float_as_uint(v)), "r"(rmbar) : "memory");
}
__device__ __forceinline__ void mbar_init(unsigned mbar, unsigned cnt) {
    asm volatile("mbarrier.init.shared.b64 [%0], %1;" :: "r"(mbar), "r"(cnt) : "memory");
}
__device__ __forceinline__ void mbar_expect_tx(unsigned mbar, unsigned bytes) {
    asm volatile("mbarrier.arrive.expect_tx.shared.b64 _, [%0], %1;"
                 :: "r"(mbar), "r"(bytes) : "memory");
}
__device__ __forceinline__ void mbar_wait_cluster(unsigned mbar, unsigned parity) {
    asm volatile(
        "{\n\t"
        ".reg .pred P;\n"
        "LWAIT_%=:\n\t"
        "mbarrier.try_wait.parity.acquire.cluster.shared::cta.b64 P, [%0], %1, 0x989680;\n\t"
        "@P bra LDONE_%=;\n\t"
        "bra LWAIT_%=;\n"
        "LDONE_%=:\n\t"
        "}"
        :: "r"(mbar), "r"(parity) : "memory");
}

// ---------------- scratch (static device globals) ----------------
__device__ float g_xw[(size_t)BATCH * TLEN * G4];     // 512 MB, reused by both layers
__device__ float g_hseq[(size_t)BATCH * TLEN * HID];  // 128 MB
__device__ float g_hlast[BATCH * HID];

// ---------------------------------------------------------------------------
// GEMM: C[M,1024] = A[M,K] @ B[K,1024] + bias, M=131072, K in {128,256}
// 128x128 tile, BK=16, 256 threads, 8x8 micro-tile, FFMA2, double-buffered.
// ---------------------------------------------------------------------------
__global__ __launch_bounds__(256, 2)
void gemm_bias_kernel(const float* __restrict__ A, const float* __restrict__ B,
                      const float* __restrict__ bias, float* __restrict__ C, int K)
{
    const int N = G4;
    __shared__ float As[2][16][128];
    __shared__ float Bs[2][16][128];

    const int tid = threadIdx.x;
    const int n0  = blockIdx.x * 128;
    const size_t m0 = (size_t)blockIdx.y * 128;
    const int tn = tid & 15;
    const int tm = tid >> 4;

    float4 av[2], bv[2];
    const int NKB = K >> 4;

    auto ldg_tiles = [&](int k0) {
#pragma unroll
        for (int i = 0; i < 2; i++) {
            int idx = tid + i * 256;
            int ar = idx >> 2, kq = idx & 3;
            av[i] = *(const float4*)&A[(m0 + ar) * K + k0 + kq * 4];
            int kr = idx >> 5, nq = idx & 31;
            bv[i] = *(const float4*)&B[(size_t)(k0 + kr) * N + n0 + nq * 4];
        }
    };
    auto sts_tiles = [&](int buf) {
#pragma unroll
        for (int i = 0; i < 2; i++) {
            int idx = tid + i * 256;
            int ar = idx >> 2, kq = idx & 3;
            As[buf][kq * 4 + 0][ar] = av[i].x;
            As[buf][kq * 4 + 1][ar] = av[i].y;
            As[buf][kq * 4 + 2][ar] = av[i].z;
            As[buf][kq * 4 + 3][ar] = av[i].w;
            int kr = idx >> 5, nq = idx & 31;
            *(float4*)&Bs[buf][kr][nq * 4] = bv[i];
        }
    };

    u64 acc[8][4];
#pragma unroll
    for (int m = 0; m < 8; m++)
#pragma unroll
        for (int j = 0; j < 4; j++) acc[m][j] = 0ull;

    ldg_tiles(0);
    sts_tiles(0);
    __syncthreads();

    for (int kb = 0; kb < NKB; kb++) {
        if (kb + 1 < NKB) ldg_tiles((kb + 1) << 4);
        const int buf = kb & 1;
#pragma unroll
        for (int k = 0; k < 16; k++) {
            float4 a0 = *(const float4*)&As[buf][k][tm * 8];
            float4 a1 = *(const float4*)&As[buf][k][tm * 8 + 4];
            u64 b0v = *(const u64*)&Bs[buf][k][2 * tn];
            u64 b1v = *(const u64*)&Bs[buf][k][2 * tn + 32];
            u64 b2v = *(const u64*)&Bs[buf][k][2 * tn + 64];
            u64 b3v = *(const u64*)&Bs[buf][k][2 * tn + 96];
            float aa[8] = {a0.x, a0.y, a0.z, a0.w, a1.x, a1.y, a1.z, a1.w};
#pragma unroll
            for (int m = 0; m < 8; m++) {
                u64 am = pack2(aa[m], aa[m]);
                acc[m][0] = ffma2(am, b0v, acc[m][0]);
                acc[m][1] = ffma2(am, b1v, acc[m][1]);
                acc[m][2] = ffma2(am, b2v, acc[m][2]);
                acc[m][3] = ffma2(am, b3v, acc[m][3]);
            }
        }
        if (kb + 1 < NKB) sts_tiles(buf ^ 1);
        __syncthreads();
    }

    float bias_r[8];
#pragma unroll
    for (int j = 0; j < 4; j++) {
        bias_r[2 * j]     = bias[n0 + 2 * tn + 32 * j];
        bias_r[2 * j + 1] = bias[n0 + 2 * tn + 32 * j + 1];
    }

#pragma unroll
    for (int m = 0; m < 8; m++) {
        size_t row = m0 + tm * 8 + m;
        float* cp = &C[row * N + n0];
#pragma unroll
        for (int j = 0; j < 4; j++) {
            float2 v;
            v.x = f2lo(acc[m][j]) + bias_r[2 * j];
            v.y = f2hi(acc[m][j]) + bias_r[2 * j + 1];
            *(float2*)&cp[2 * tn + 32 * j] = v;
        }
    }
}

// ---------------------------------------------------------------------------
// Persistent-cluster LSTM recurrence, st.async exchange, TWO-GROUP PIPELINE.
// Grid: 128 CTAs = 16 clusters x 8 CTAs, 256 threads.
// Cluster cid owns batch rows [8cid, 8cid+8), split into group0 = rows 0-3,
// group1 = rows 4-7, processed half-a-step out of phase so each group's
// st.async fabric latency + cluster skew is hidden by the other group's
// phase1+epilogue compute.
// CTA rank owns 128 gate columns: col(gc) = (gc>>5)*256 + rank*32 + (gc&31).
// mbars[p*2+g]: tx barrier for (buffer p, group g); expect 4096 B each
// (4 rows x 256 cols x 4B arriving from the 8 ranks combined).
// ---------------------------------------------------------------------------
template <bool WRITE_SEQ>
__global__ void __cluster_dims__(8, 1, 1) __launch_bounds__(256, 1)
lstm_layer(const float* __restrict__ xw, const float* __restrict__ U,
           float* __restrict__ out_seq, float* __restrict__ out_last)
{
    __shared__ __align__(16) float hbuf[2][8][HID];   // 16 KB, dbl-buffered h
    __shared__ float part[2][4][4][128];              // 16 KB, [grp][kh][row][gc]
    __shared__ __align__(8) u64 mbars[4];             // [buf*2+grp]

    cg::cluster_group cluster = cg::this_cluster();
    const int tid  = threadIdx.x;
    const int rank = (int)cluster.block_rank();
    const int cid  = blockIdx.x >> 3;
    const int b0   = cid * 8;

    // phase-1 roles (R3 mapping)
    const int gcA = tid & 63;
    const int gcB = gcA + 64;
    const int kh  = tid >> 6;                 // k block [kh*64, kh*64+64)
    const int colA = (gcA >> 5) * 256 + rank * 32 + (gcA & 31);
    const int colB = (gcB >> 5) * 256 + rank * 32 + (gcB & 31);

    // epilogue roles
    const int er   = tid >> 5;                // batch row within cluster (0..7)
    const int ec   = tid & 31;                // h column within rank's 32
    const int egrp = er >> 2;                 // this thread's epilogue group
    const int erow = er & 3;                  // row within group

    // U slice in registers: 32 k-pairs x 2 columns
    u64 u2a[32], u2b[32];
#pragma unroll
    for (int kp = 0; kp < 32; kp++) {
        int k = kh * 64 + 2 * kp;
        u2a[kp] = pack2(U[(size_t)k * G4 + colA], U[(size_t)(k + 1) * G4 + colA]);
        u2b[kp] = pack2(U[(size_t)k * G4 + colB], U[(size_t)(k + 1) * G4 + colB]);
    }

    // init smem
    for (int i = tid; i < 2 * 8 * HID; i += 256) ((float*)hbuf)[i] = 0.f;
    const unsigned mbar0 = smem_u32(&mbars[0]);
    if (tid == 0) {
#pragma unroll
        for (int i = 0; i < 4; i++) mbar_init(mbar0 + 8u * i, 1);
    }

    // per-rank remote addresses
    const unsigned hloc = smem_u32(&hbuf[0][er][rank * 32 + ec]);
    unsigned rH[8], rM[8];
#pragma unroll
    for (int pr = 0; pr < 8; pr++) {
        rH[pr] = mapa_u32(hloc, pr);
        rM[pr] = mapa_u32(mbar0, pr);
    }

    cluster.sync();   // barriers + zeroed hbuf visible cluster-wide
    if (tid == 0) {
#pragma unroll
        for (int i = 0; i < 4; i++) mbar_expect_tx(mbar0 + 8u * i, 4096);
    }

    const float* xptr = xw + ((size_t)(b0 + er) * TLEN) * G4 + rank * 32 + ec;
    float* hptr = WRITE_SEQ
        ? out_seq + ((size_t)(b0 + er) * TLEN) * HID + rank * 32 + ec
        : nullptr;

    float c_state = 0.f;
    unsigned pp00 = 0, pp01 = 0, pp10 = 0, pp11 = 0;  // parity[buf][grp]

    for (int t = 0; t < TLEN; t++) {
        const int p  = t & 1;
        const int nb = p ^ 1;
        const unsigned hoff = (unsigned)(nb * 8 * HID) * 4u;
        const unsigned moffG = (unsigned)(nb * 2 + egrp) * 8u;

        // prefetch own row's xw gate inputs (consumed in own group's epilogue)
        float xg0 = xptr[0];
        float xg1 = xptr[HID];
        float xg2 = xptr[2 * HID];
        float xg3 = xptr[3 * HID];
        xptr += G4;

#pragma unroll
        for (int g = 0; g < 2; g++) {
            // ---- wait for this buffer+group's h from all ranks ----
            if (t > 0) {
                const unsigned mb = mbar0 + (unsigned)(p * 2 + g) * 8u;
                if (p == 0) {
                    if (g == 0) { mbar_wait_cluster(mb, pp00); pp00 ^= 1; }
                    else        { mbar_wait_cluster(mb, pp01); pp01 ^= 1; }
                } else {
                    if (g == 0) { mbar_wait_cluster(mb, pp10); pp10 ^= 1; }
                    else        { mbar_wait_cluster(mb, pp11); pp11 ^= 1; }
                }
                if (tid == 0) mbar_expect_tx(mb, 4096);   // re-arm
            }

            // ---- phase 1 for this group's 4 rows ----
            u64 accA[4], accB[4];
#pragma unroll
            for (int r = 0; r < 4; r++) { accA[r] = 0ull; accB[r] = 0ull; }

#pragma unroll
            for (int kq = 0; kq < 16; kq++) {
                const int k = kh * 64 + kq * 4;
                float4 h4[4];
#pragma unroll
                for (int r = 0; r < 4; r++)
                    h4[r] = *(const float4*)&hbuf[p][g * 4 + r][k];
                u64 ua0 = u2a[2 * kq], ua1 = u2a[2 * kq + 1];
                u64 ub0 = u2b[2 * kq], ub1 = u2b[2 * kq + 1];
#pragma unroll
                for (int r = 0; r < 4; r++) {
                    u64 hlo = pack2(h4[r].x, h4[r].y);
                    u64 hhi = pack2(h4[r].z, h4[r].w);
                    accA[r] = ffma2(hlo, ua0, accA[r]);
                    accA[r] = ffma2(hhi, ua1, accA[r]);
                    accB[r] = ffma2(hlo, ub0, accB[r]);
                    accB[r] = ffma2(hhi, ub1, accB[r]);
                }
            }
#pragma unroll
            for (int r = 0; r < 4; r++) {
                part[g][kh][r][gcA] = f2lo(accA[r]) + f2hi(accA[r]);
                part[g][kh][r][gcB] = f2lo(accB[r]) + f2hi(accB[r]);
            }
            __syncthreads();

            // ---- epilogue for this group (warps whose rows belong to it) ----
            if (egrp == g) {
                float v0 = xg0, v1 = xg1, v2 = xg2, v3 = xg3;
#pragma unroll
                for (int q = 0; q < 4; q++) {
                    v0 += part[g][q][erow][ec];
                    v1 += part[g][q][erow][32 + ec];
                    v2 += part[g][q][erow][64 + ec];
                    v3 += part[g][q][erow][96 + ec];
                }
                float ig = sigm_f(v0);
                float fg = sigm_f(v1);
                float gg = tanh_f(v2);
                float og = sigm_f(v3);
                c_state = fg * c_state + ig * gg;
                float hnew = og * tanh_f(c_state);

                if (WRITE_SEQ) { *hptr = hnew; hptr += HID; }

                if (t < TLEN - 1) {
#pragma unroll
                    for (int pr = 0; pr < 8; pr++)
                        st_async_f32(rH[pr] + hoff, hnew, rM[pr] + moffG);
                } else if (!WRITE_SEQ) {
                    out_last[(size_t)(b0 + er) * HID + rank * 32 + ec] = hnew;
                }
            }
        }
    }

    cluster.sync();   // don't exit with peer-targeted async traffic in flight
}

// ---------------------------------------------------------------------------
// Dense head: out[b] = relu( relu(h_last[b] @ Wd1 + bd1) @ Wd2 + bd2 )
// ---------------------------------------------------------------------------
__global__ __launch_bounds__(128)
void dense_head_kernel(const float* __restrict__ hlast,
                       const float* __restrict__ Wd1, const float* __restrict__ bd1,
                       const float* __restrict__ Wd2, const float* __restrict__ bd2,
                       float* __restrict__ out)
{
    __shared__ float hs[HID];
    __shared__ float red[4];
    const int b = blockIdx.x;
    const int j = threadIdx.x;

    hs[j]       = hlast[b * HID + j];
    hs[j + 128] = hlast[b * HID + j + 128];
    __syncthreads();

    float acc = bd1[j];
#pragma unroll 8
    for (int k = 0; k < HID; k++) acc = fmaf(hs[k], Wd1[k * 128 + j], acc);
    float hm = fmaxf(acc, 0.f) * Wd2[j];

#pragma unroll
    for (int off = 16; off > 0; off >>= 1)
        hm += __shfl_down_sync(0xffffffffu, hm, off);
    if ((j & 31) == 0) red[j >> 5] = hm;
    __syncthreads();
    if (j == 0) {
        float s = red[0] + red[1] + red[2] + red[3] + bd2[0];
        out[b] = fmaxf(s, 0.f);
    }
}

// ---------------------------------------------------------------------------
extern "C" void kernel_launch(void* const* d_in, const int* in_sizes, int n_in,
                              void* d_out, int out_size)
{
    const float* x   = (const float*)d_in[0];
    const float* W1  = (const float*)d_in[1];
    const float* U1  = (const float*)d_in[2];
    const float* b1  = (const float*)d_in[3];
    const float* W2  = (const float*)d_in[4];
    const float* U2  = (const float*)d_in[5];
    const float* b2  = (const float*)d_in[6];
    const float* Wd1 = (const float*)d_in[7];
    const float* bd1 = (const float*)d_in[8];
    const float* Wd2 = (const float*)d_in[9];
    const float* bd2 = (const float*)d_in[10];
    float* out = (float*)d_out;

    float *xw, *hseq, *hlast;
    cudaGetSymbolAddress((void**)&xw, g_xw);
    cudaGetSymbolAddress((void**)&hseq, g_hseq);
    cudaGetSymbolAddress((void**)&hlast, g_hlast);

    dim3 ggrid(G4 / 128, (BATCH * TLEN) / 128);

    gemm_bias_kernel<<<ggrid, 256>>>(x, W1, b1, xw, 128);
    lstm_layer<true><<<128, 256>>>(xw, U1, hseq, nullptr);
    gemm_bias_kernel<<<ggrid, 256>>>(hseq, W2, b2, xw, 256);
    lstm_layer<false><<<128, 256>>>(xw, U2, nullptr, hlast);
    dense_head_kernel<<<BATCH, 128>>>(hlast, Wd1, bd1, Wd2, bd2, out);
}